// round 4
// baseline (speedup 1.0000x reference)
#include <cuda_runtime.h>
#include <math.h>
#include <cstdint>

// Problem constants
#define TOK    4096
#define DMODEL 1024
#define NEXP   8
#define HDIM   4096
#define NASSIGN (TOK*2)

// GEMM tiling
#define BM 128
#define BN 256
#define BK 32
#define NSTAGE 4
#define LDA 36            // floats (bank = 4g+tig, conflict-free)
#define LDB 264           // floats (bank = 8tig+g, conflict-free; 264%32==8)
#define A_BYTES (BM*LDA*4)                 // 18432
#define B_BYTES (BK*LDB*4)                 // 33792
#define STAGE_BYTES (A_BYTES + B_BYTES)    // 52224
#define SMEM_TOTAL (NSTAGE*STAGE_BYTES)    // 208896

// Scratch (device globals; allocation-free rule)
__device__ int   g_expert_off[NEXP+1];
__device__ int   g_perm_tok[NASSIGN];
__device__ int   g_inv_pos[NASSIGN];
__device__ int   g_tok_exp[NASSIGN];
__device__ float g_tok_gate[NASSIGN];
__device__ float g_xt[(size_t)TOK * DMODEL];          // tf32-rounded x
__device__ float g_wfct[(size_t)NEXP * DMODEL * HDIM];   // tf32-rounded w_fc
__device__ float g_wprojt[(size_t)NEXP * HDIM * DMODEL]; // tf32-rounded w_proj
__device__ float g_hbuf[(size_t)NASSIGN * HDIM];      // tf32-rounded activations
__device__ float g_ybuf[(size_t)NASSIGN * DMODEL];

// ---------------------------------------------------------------------------
__device__ __forceinline__ uint32_t smem_u32(const void* p) {
    uint32_t a;
    asm("{ .reg .u64 t; cvta.to.shared.u64 t, %1; cvt.u32.u64 %0, t; }" : "=r"(a) : "l"(p));
    return a;
}
__device__ __forceinline__ uint32_t cvt_tf32(float x) {
    uint32_t r; asm("cvt.rna.tf32.f32 %0, %1;" : "=r"(r) : "f"(x)); return r;
}
__device__ __forceinline__ float tf32f(float x) { return __uint_as_float(cvt_tf32(x)); }

#define CP_ASYNC16(dst, src) \
    asm volatile("cp.async.cg.shared.global [%0], [%1], 16;" :: "r"(dst), "l"(src))
#define CP_COMMIT() asm volatile("cp.async.commit_group;")
#define CP_WAIT2()  asm volatile("cp.async.wait_group 2;")

__device__ __forceinline__ void mma_tf32(float* c, const uint32_t* a, const uint32_t* b) {
    asm volatile(
        "mma.sync.aligned.m16n8k8.row.col.f32.tf32.tf32.f32 "
        "{%0,%1,%2,%3}, {%4,%5,%6,%7}, {%8,%9}, {%0,%1,%2,%3};"
        : "+f"(c[0]), "+f"(c[1]), "+f"(c[2]), "+f"(c[3])
        : "r"(a[0]), "r"(a[1]), "r"(a[2]), "r"(a[3]), "r"(b[0]), "r"(b[1]));
}

__device__ __forceinline__ float gelu_tanh(float v) {
    const float c = 0.7978845608028654f;
    float u = c * (v + 0.044715f * v * v * v);
    return 0.5f * v * (1.0f + tanhf(u));
}

// ---------------------------------------------------------------------------
// tf32 rounding prep (grid-stride float4)
// ---------------------------------------------------------------------------
__global__ void __launch_bounds__(256) round_kernel(const float* __restrict__ src,
                                                    float* __restrict__ dst, int n4)
{
    int i = blockIdx.x * blockDim.x + threadIdx.x;
    int stride = gridDim.x * blockDim.x;
    for (; i < n4; i += stride) {
        float4 v = reinterpret_cast<const float4*>(src)[i];
        v.x = tf32f(v.x); v.y = tf32f(v.y); v.z = tf32f(v.z); v.w = tf32f(v.w);
        reinterpret_cast<float4*>(dst)[i] = v;
    }
}

// ---------------------------------------------------------------------------
// Router: one warp per token
// ---------------------------------------------------------------------------
__global__ void __launch_bounds__(256) router_kernel(
    const float* __restrict__ x, const float* __restrict__ noise,
    const float* __restrict__ wr, const float* __restrict__ br,
    const float* __restrict__ wn, const float* __restrict__ bn,
    float* __restrict__ gate1)
{
    int warp = (blockIdx.x * blockDim.x + threadIdx.x) >> 5;
    int lane = threadIdx.x & 31;
    if (warp >= TOK) return;

    const float* xr = x + (size_t)warp * DMODEL;
    float ar[8] = {0,0,0,0,0,0,0,0};
    float an[8] = {0,0,0,0,0,0,0,0};

    #pragma unroll 8
    for (int j = 0; j < DMODEL/32; j++) {
        int d = j*32 + lane;
        float xv = xr[d];
        const float4* w4r = reinterpret_cast<const float4*>(wr + (size_t)d*8);
        const float4* w4n = reinterpret_cast<const float4*>(wn + (size_t)d*8);
        float4 r0 = w4r[0], r1 = w4r[1];
        float4 n0 = w4n[0], n1 = w4n[1];
        ar[0] = fmaf(xv, r0.x, ar[0]); ar[1] = fmaf(xv, r0.y, ar[1]);
        ar[2] = fmaf(xv, r0.z, ar[2]); ar[3] = fmaf(xv, r0.w, ar[3]);
        ar[4] = fmaf(xv, r1.x, ar[4]); ar[5] = fmaf(xv, r1.y, ar[5]);
        ar[6] = fmaf(xv, r1.z, ar[6]); ar[7] = fmaf(xv, r1.w, ar[7]);
        an[0] = fmaf(xv, n0.x, an[0]); an[1] = fmaf(xv, n0.y, an[1]);
        an[2] = fmaf(xv, n0.z, an[2]); an[3] = fmaf(xv, n0.w, an[3]);
        an[4] = fmaf(xv, n1.x, an[4]); an[5] = fmaf(xv, n1.y, an[5]);
        an[6] = fmaf(xv, n1.z, an[6]); an[7] = fmaf(xv, n1.w, an[7]);
    }
    #pragma unroll
    for (int e = 0; e < 8; e++) {
        #pragma unroll
        for (int o = 16; o > 0; o >>= 1) {
            ar[e] += __shfl_xor_sync(0xffffffffu, ar[e], o);
            an[e] += __shfl_xor_sync(0xffffffffu, an[e], o);
        }
    }
    if (lane == 0) {
        float nv[8];
        float mx = -1e30f;
        #pragma unroll
        for (int e = 0; e < 8; e++) {
            float l  = ar[e] + br[e];
            float nl = an[e] + bn[e];
            float sp = fmaxf(nl, 0.0f) + log1pf(expf(-fabsf(nl)));
            float v = l + noise[(size_t)warp*8 + e] * sp;
            nv[e] = v;
            mx = fmaxf(mx, v);
        }
        float s = 0.0f;
        #pragma unroll
        for (int e = 0; e < 8; e++) s += expf(nv[e] - mx);
        float inv = 1.0f / s;
        #pragma unroll
        for (int e = 0; e < 8; e++) gate1[(size_t)warp*8 + e] = expf(nv[e] - mx) * inv;
        int i0 = 0;
        #pragma unroll
        for (int e = 1; e < 8; e++) if (nv[e] > nv[i0]) i0 = e;
        int i1 = -1;
        #pragma unroll
        for (int e = 0; e < 8; e++) {
            if (e == i0) continue;
            if (i1 < 0 || nv[e] > nv[i1]) i1 = e;
        }
        float ex = expf(nv[i1] - nv[i0]);
        float den = 1.0f + ex;
        g_tok_exp[warp*2 + 0]  = i0;
        g_tok_exp[warp*2 + 1]  = i1;
        g_tok_gate[warp*2 + 0] = 1.0f / den;
        g_tok_gate[warp*2 + 1] = ex / den;
    }
}

// ---------------------------------------------------------------------------
// Deterministic stable partition + inverse permutation
// ---------------------------------------------------------------------------
__global__ void __launch_bounds__(256) partition_kernel()
{
    __shared__ int cnt[256][8];
    __shared__ int tot[8];
    __shared__ int base[9];
    int tid = threadIdx.x;
    int a0 = tid * 32;

    int local[8] = {0,0,0,0,0,0,0,0};
    for (int i = 0; i < 32; i++) local[g_tok_exp[a0 + i]]++;
    #pragma unroll
    for (int e = 0; e < 8; e++) cnt[tid][e] = local[e];
    __syncthreads();

    if (tid < 8) {
        int run = 0;
        for (int i = 0; i < 256; i++) { int v = cnt[i][tid]; cnt[i][tid] = run; run += v; }
        tot[tid] = run;
    }
    __syncthreads();
    if (tid == 0) {
        int acc = 0;
        for (int e = 0; e < 8; e++) { base[e] = acc; acc += tot[e]; }
        base[8] = acc;
        for (int e = 0; e <= 8; e++) g_expert_off[e] = base[e];
    }
    __syncthreads();

    int run2[8];
    #pragma unroll
    for (int e = 0; e < 8; e++) run2[e] = base[e] + cnt[tid][e];
    for (int i = 0; i < 32; i++) {
        int a = a0 + i;
        int e = g_tok_exp[a];
        int p = run2[e]++;
        g_perm_tok[p] = a >> 1;
        g_inv_pos[a]  = p;
    }
}

// ---------------------------------------------------------------------------
// tf32 mma.sync GEMM, 128x256 tile, BK=32, cp.async 4-stage pipeline.
// All inputs pre-rounded to tf32 in gmem -> mainloop is pure LDS + MMA.
// IS_FC: A = gathered g_xt rows (K=1024), Out = tf32(gelu(D+b)) -> g_hbuf
// else:  A = g_hbuf rows (K=4096),        Out = D + b          -> g_ybuf
// ---------------------------------------------------------------------------
template<int K, int NTOT, bool IS_FC>
__global__ void __launch_bounds__(256) moe_gemm_kernel(
    const float* __restrict__ Ain,
    const float* __restrict__ W,
    const float* __restrict__ bias)
{
    constexpr int NCH = K / BK;
    extern __shared__ char smem[];

    int e = blockIdx.y >> 6, m = blockIdx.y & 63;
    int off = g_expert_off[e];
    int cnt = g_expert_off[e+1] - off;
    if (m * BM >= cnt) return;
    int mbase = off + m * BM;
    int rv = min(cnt - m * BM, BM);
    int n0 = blockIdx.x * BN;

    int tid = threadIdx.x;
    int wid = tid >> 5, lane = tid & 31;
    int wm = wid & 1, wn = wid >> 1;          // 2 x 4 warp grid, warp tile 64x64
    int g = lane >> 2, tig = lane & 3;

    uint32_t sbase = smem_u32(smem);
    const float* A = IS_FC ? Ain : g_hbuf;
    const float* wbase = W + (size_t)e * K * NTOT + n0;

    // A: 128 rows x 32 floats = 1024 x 16B chunks, 4 per thread
    const char* aSrc[4];
    uint32_t aDst0 = (uint32_t)((tid >> 3) * (LDA*4) + (tid & 7) * 16);
    #pragma unroll
    for (int i = 0; i < 4; i++) {
        int row = i*32 + (tid >> 3);
        int r = min(row, rv - 1);
        int arow = IS_FC ? g_perm_tok[mbase + r] : (mbase + r);
        aSrc[i] = (const char*)(A + (size_t)arow * K) + (tid & 7) * 16;
    }
    // B: 32 rows x 256 floats = 2048 x 16B chunks, 8 per thread (4 rows per i-step)
    const char* bSrc0 = (const char*)(wbase + (size_t)(tid >> 6) * NTOT) + (tid & 63) * 16;
    uint32_t bDst0 = (uint32_t)((tid >> 6) * (LDB*4) + (tid & 63) * 16);

    float acc[4][8][4];
    #pragma unroll
    for (int i = 0; i < 4; i++)
        #pragma unroll
        for (int j = 0; j < 8; j++)
            #pragma unroll
            for (int v = 0; v < 4; v++) acc[i][j][v] = 0.0f;

    auto issue = [&](int kt) {
        uint32_t base = sbase + (uint32_t)(kt & 3) * STAGE_BYTES;
        #pragma unroll
        for (int i = 0; i < 4; i++)
            CP_ASYNC16(base + aDst0 + i * (32*LDA*4), aSrc[i] + (size_t)kt * (BK*4));
        #pragma unroll
        for (int i = 0; i < 8; i++)
            CP_ASYNC16(base + A_BYTES + bDst0 + i * (4*LDB*4),
                       bSrc0 + (size_t)kt * ((size_t)BK * NTOT * 4) + (size_t)i * (4*(size_t)NTOT*4));
    };

    issue(0); CP_COMMIT();
    issue(1); CP_COMMIT();
    issue(2); CP_COMMIT();

    for (int kt = 0; kt < NCH; kt++) {
        CP_WAIT2();
        __syncthreads();
        if (kt + 3 < NCH) issue(kt + 3);
        CP_COMMIT();

        const uint32_t* As = (const uint32_t*)(smem + (kt & 3) * STAGE_BYTES);
        const uint32_t* Bs = (const uint32_t*)(smem + (kt & 3) * STAGE_BYTES + A_BYTES);

        #pragma unroll
        for (int ks = 0; ks < 4; ks++) {
            uint32_t af[4][4], bf[8][2];
            #pragma unroll
            for (int mf = 0; mf < 4; mf++) {
                const uint32_t* p = As + (wm*64 + mf*16 + g) * LDA + ks*8 + tig;
                af[mf][0] = p[0];
                af[mf][2] = p[4];
                af[mf][1] = p[8*LDA];
                af[mf][3] = p[8*LDA + 4];
            }
            #pragma unroll
            for (int nf = 0; nf < 8; nf++) {
                const uint32_t* p = Bs + (ks*8 + tig) * LDB + wn*64 + nf*8 + g;
                bf[nf][0] = p[0];
                bf[nf][1] = p[4*LDB];
            }
            #pragma unroll
            for (int mf = 0; mf < 4; mf++)
                #pragma unroll
                for (int nf = 0; nf < 8; nf++)
                    mma_tf32(acc[mf][nf], af[mf], bf[nf]);
        }
    }

    // ---- epilogue ----
    float* Out = IS_FC ? g_hbuf : g_ybuf;
    const float* brow = bias + (size_t)e * NTOT + n0;

    #pragma unroll
    for (int mf = 0; mf < 4; mf++) {
        int r0 = wm*64 + mf*16 + g;
        int r1 = r0 + 8;
        float* o0 = Out + (size_t)(mbase + r0) * NTOT + n0;
        float* o1 = Out + (size_t)(mbase + r1) * NTOT + n0;
        #pragma unroll
        for (int nf = 0; nf < 8; nf++) {
            int col = wn*64 + nf*8 + tig*2;
            float2 bb = *reinterpret_cast<const float2*>(brow + col);
            if (r0 < rv) {
                float v0 = acc[mf][nf][0] + bb.x;
                float v1 = acc[mf][nf][1] + bb.y;
                float2 o;
                if (IS_FC) { o.x = tf32f(gelu_tanh(v0)); o.y = tf32f(gelu_tanh(v1)); }
                else       { o.x = v0;                   o.y = v1; }
                *reinterpret_cast<float2*>(o0 + col) = o;
            }
            if (r1 < rv) {
                float v2 = acc[mf][nf][2] + bb.x;
                float v3 = acc[mf][nf][3] + bb.y;
                float2 o;
                if (IS_FC) { o.x = tf32f(gelu_tanh(v2)); o.y = tf32f(gelu_tanh(v3)); }
                else       { o.x = v2;                   o.y = v3; }
                *reinterpret_cast<float2*>(o1 + col) = o;
            }
        }
    }
}

// ---------------------------------------------------------------------------
// Combine: out[t] = g0 * y[p0] + g1 * y[p1]
// ---------------------------------------------------------------------------
__global__ void __launch_bounds__(256) combine_kernel(float* __restrict__ out)
{
    int t = blockIdx.x;
    int j = threadIdx.x;
    int p0 = g_inv_pos[2*t], p1 = g_inv_pos[2*t+1];
    float g0 = g_tok_gate[2*t], g1 = g_tok_gate[2*t+1];
    const float4* y0 = reinterpret_cast<const float4*>(g_ybuf + (size_t)p0 * DMODEL);
    const float4* y1 = reinterpret_cast<const float4*>(g_ybuf + (size_t)p1 * DMODEL);
    float4 a = y0[j], b = y1[j];
    float4 o;
    o.x = g0*a.x + g1*b.x; o.y = g0*a.y + g1*b.y;
    o.z = g0*a.z + g1*b.z; o.w = g0*a.w + g1*b.w;
    reinterpret_cast<float4*>(out + (size_t)t * DMODEL)[j] = o;
}

// ---------------------------------------------------------------------------
extern "C" void kernel_launch(void* const* d_in, const int* in_sizes, int n_in,
                              void* d_out, int out_size)
{
    const float* x      = (const float*)d_in[0];
    const float* noise  = (const float*)d_in[1];
    const float* wroute = (const float*)d_in[2];
    const float* broute = (const float*)d_in[3];
    const float* wnoise = (const float*)d_in[4];
    const float* bnoise = (const float*)d_in[5];
    const float* wfc    = (const float*)d_in[6];
    const float* bfc    = (const float*)d_in[7];
    const float* wproj  = (const float*)d_in[8];
    const float* bproj  = (const float*)d_in[9];

    float* out   = (float*)d_out;
    float* gate1 = out + (size_t)TOK * DMODEL;

    cudaFuncSetAttribute((const void*)moe_gemm_kernel<DMODEL, HDIM, true>,
        cudaFuncAttributeMaxDynamicSharedMemorySize, SMEM_TOTAL);
    cudaFuncSetAttribute((const void*)moe_gemm_kernel<HDIM, DMODEL, false>,
        cudaFuncAttributeMaxDynamicSharedMemorySize, SMEM_TOTAL);

    // resolve device-global scratch addresses
    float *xt_p, *wfct_p, *wprojt_p;
    cudaGetSymbolAddress((void**)&xt_p, g_xt);
    cudaGetSymbolAddress((void**)&wfct_p, g_wfct);
    cudaGetSymbolAddress((void**)&wprojt_p, g_wprojt);

    // tf32 pre-rounding
    round_kernel<<<1184, 256>>>(x, xt_p, TOK*DMODEL/4);
    round_kernel<<<4736, 256>>>(wfc, wfct_p, NEXP*DMODEL*HDIM/4);
    round_kernel<<<4736, 256>>>(wproj, wprojt_p, NEXP*HDIM*DMODEL/4);

    router_kernel<<<TOK/8, 256>>>(x, noise, wroute, broute, wnoise, bnoise, gate1);
    partition_kernel<<<1, 256>>>();

    dim3 g1(HDIM / BN, NEXP * 64);     // 16 x 512
    moe_gemm_kernel<DMODEL, HDIM, true><<<g1, 256, SMEM_TOTAL>>>(xt_p, wfct_p, bfc);

    dim3 g2(DMODEL / BN, NEXP * 64);   // 4 x 512
    moe_gemm_kernel<HDIM, DMODEL, false><<<g2, 256, SMEM_TOTAL>>>(xt_p, wprojt_p, bproj);

    combine_kernel<<<TOK, 256>>>(out);
}

// round 5
// speedup vs baseline: 1.8482x; 1.8482x over previous
#include <cuda_runtime.h>
#include <cuda_fp16.h>
#include <math.h>
#include <cstdint>

// Problem constants
#define TOK    4096
#define DMODEL 1024
#define NEXP   8
#define HDIM   4096
#define NASSIGN (TOK*2)

#define BM 128
#define BK 32              // k-extent per stage (halves)
#define NSTAGE 5
#define A_BYTES 8192       // 128 rows x 32 halves (64B/row)

// Scratch (device globals; allocation-free rule)
__device__ int    g_expert_off[NEXP+1];
__device__ int    g_perm_tok[NASSIGN];
__device__ int    g_inv_pos[NASSIGN];
__device__ int    g_tok_exp[NASSIGN];
__device__ float  g_tok_gate[NASSIGN];
__device__ __half g_xh[(size_t)TOK * DMODEL];
__device__ __half g_wfch[(size_t)NEXP * DMODEL * HDIM];
__device__ __half g_wprojh[(size_t)NEXP * HDIM * DMODEL];
__device__ __half g_hbufh[(size_t)NASSIGN * HDIM];
__device__ float  g_ybuf[(size_t)NASSIGN * DMODEL];

// ---------------------------------------------------------------------------
__device__ __forceinline__ uint32_t smem_u32(const void* p) {
    uint32_t a;
    asm("{ .reg .u64 t; cvta.to.shared.u64 t, %1; cvt.u32.u64 %0, t; }" : "=r"(a) : "l"(p));
    return a;
}
#define CP_ASYNC16(dst, src) \
    asm volatile("cp.async.cg.shared.global [%0], [%1], 16;" :: "r"(dst), "l"(src))
#define CP_COMMIT() asm volatile("cp.async.commit_group;")
#define CP_WAIT3()  asm volatile("cp.async.wait_group 3;")

#define LDSM_X4(R0,R1,R2,R3,ADDR) \
    asm volatile("ldmatrix.sync.aligned.m8n8.x4.shared.b16 {%0,%1,%2,%3}, [%4];" \
        : "=r"(R0),"=r"(R1),"=r"(R2),"=r"(R3) : "r"(ADDR))
#define LDSM_X4_T(R0,R1,R2,R3,ADDR) \
    asm volatile("ldmatrix.sync.aligned.m8n8.x4.trans.shared.b16 {%0,%1,%2,%3}, [%4];" \
        : "=r"(R0),"=r"(R1),"=r"(R2),"=r"(R3) : "r"(ADDR))

__device__ __forceinline__ void mma_fp16(float* c, const uint32_t* a, const uint32_t* b) {
    asm volatile(
        "mma.sync.aligned.m16n8k16.row.col.f32.f16.f16.f32 "
        "{%0,%1,%2,%3}, {%4,%5,%6,%7}, {%8,%9}, {%0,%1,%2,%3};"
        : "+f"(c[0]), "+f"(c[1]), "+f"(c[2]), "+f"(c[3])
        : "r"(a[0]), "r"(a[1]), "r"(a[2]), "r"(a[3]), "r"(b[0]), "r"(b[1]));
}

__device__ __forceinline__ float gelu_tanh(float v) {
    const float c = 0.7978845608028654f;
    float u = c * (v + 0.044715f * v * v * v);
    return 0.5f * v * (1.0f + tanhf(u));
}

// ---------------------------------------------------------------------------
// fp32 -> fp16 conversion (grid-stride, float4 -> half2x2)
// ---------------------------------------------------------------------------
__global__ void __launch_bounds__(256) conv_half_kernel(const float* __restrict__ src,
                                                        __half* __restrict__ dst, int n4)
{
    int i = blockIdx.x * blockDim.x + threadIdx.x;
    int stride = gridDim.x * blockDim.x;
    for (; i < n4; i += stride) {
        float4 v = reinterpret_cast<const float4*>(src)[i];
        __half2 h0 = __floats2half2_rn(v.x, v.y);
        __half2 h1 = __floats2half2_rn(v.z, v.w);
        reinterpret_cast<__half2*>(dst)[2*i]   = h0;
        reinterpret_cast<__half2*>(dst)[2*i+1] = h1;
    }
}

// ---------------------------------------------------------------------------
// Router: one warp per token (fp32, exact)
// ---------------------------------------------------------------------------
__global__ void __launch_bounds__(256) router_kernel(
    const float* __restrict__ x, const float* __restrict__ noise,
    const float* __restrict__ wr, const float* __restrict__ br,
    const float* __restrict__ wn, const float* __restrict__ bn,
    float* __restrict__ gate1)
{
    int warp = (blockIdx.x * blockDim.x + threadIdx.x) >> 5;
    int lane = threadIdx.x & 31;
    if (warp >= TOK) return;

    const float* xr = x + (size_t)warp * DMODEL;
    float ar[8] = {0,0,0,0,0,0,0,0};
    float an[8] = {0,0,0,0,0,0,0,0};

    #pragma unroll 8
    for (int j = 0; j < DMODEL/32; j++) {
        int d = j*32 + lane;
        float xv = xr[d];
        const float4* w4r = reinterpret_cast<const float4*>(wr + (size_t)d*8);
        const float4* w4n = reinterpret_cast<const float4*>(wn + (size_t)d*8);
        float4 r0 = w4r[0], r1 = w4r[1];
        float4 n0 = w4n[0], n1 = w4n[1];
        ar[0] = fmaf(xv, r0.x, ar[0]); ar[1] = fmaf(xv, r0.y, ar[1]);
        ar[2] = fmaf(xv, r0.z, ar[2]); ar[3] = fmaf(xv, r0.w, ar[3]);
        ar[4] = fmaf(xv, r1.x, ar[4]); ar[5] = fmaf(xv, r1.y, ar[5]);
        ar[6] = fmaf(xv, r1.z, ar[6]); ar[7] = fmaf(xv, r1.w, ar[7]);
        an[0] = fmaf(xv, n0.x, an[0]); an[1] = fmaf(xv, n0.y, an[1]);
        an[2] = fmaf(xv, n0.z, an[2]); an[3] = fmaf(xv, n0.w, an[3]);
        an[4] = fmaf(xv, n1.x, an[4]); an[5] = fmaf(xv, n1.y, an[5]);
        an[6] = fmaf(xv, n1.z, an[6]); an[7] = fmaf(xv, n1.w, an[7]);
    }
    #pragma unroll
    for (int e = 0; e < 8; e++) {
        #pragma unroll
        for (int o = 16; o > 0; o >>= 1) {
            ar[e] += __shfl_xor_sync(0xffffffffu, ar[e], o);
            an[e] += __shfl_xor_sync(0xffffffffu, an[e], o);
        }
    }
    if (lane == 0) {
        float nv[8];
        float mx = -1e30f;
        #pragma unroll
        for (int e = 0; e < 8; e++) {
            float l  = ar[e] + br[e];
            float nl = an[e] + bn[e];
            float sp = fmaxf(nl, 0.0f) + log1pf(expf(-fabsf(nl)));
            float v = l + noise[(size_t)warp*8 + e] * sp;
            nv[e] = v;
            mx = fmaxf(mx, v);
        }
        float s = 0.0f;
        #pragma unroll
        for (int e = 0; e < 8; e++) s += expf(nv[e] - mx);
        float inv = 1.0f / s;
        #pragma unroll
        for (int e = 0; e < 8; e++) gate1[(size_t)warp*8 + e] = expf(nv[e] - mx) * inv;
        int i0 = 0;
        #pragma unroll
        for (int e = 1; e < 8; e++) if (nv[e] > nv[i0]) i0 = e;
        int i1 = -1;
        #pragma unroll
        for (int e = 0; e < 8; e++) {
            if (e == i0) continue;
            if (i1 < 0 || nv[e] > nv[i1]) i1 = e;
        }
        float ex = expf(nv[i1] - nv[i0]);
        float den = 1.0f + ex;
        g_tok_exp[warp*2 + 0]  = i0;
        g_tok_exp[warp*2 + 1]  = i1;
        g_tok_gate[warp*2 + 0] = 1.0f / den;
        g_tok_gate[warp*2 + 1] = ex / den;
    }
}

// ---------------------------------------------------------------------------
// Deterministic stable partition + inverse permutation
// ---------------------------------------------------------------------------
__global__ void __launch_bounds__(256) partition_kernel()
{
    __shared__ int cnt[256][8];
    __shared__ int tot[8];
    __shared__ int base[9];
    int tid = threadIdx.x;
    int a0 = tid * 32;

    int local[8] = {0,0,0,0,0,0,0,0};
    for (int i = 0; i < 32; i++) local[g_tok_exp[a0 + i]]++;
    #pragma unroll
    for (int e = 0; e < 8; e++) cnt[tid][e] = local[e];
    __syncthreads();

    if (tid < 8) {
        int run = 0;
        for (int i = 0; i < 256; i++) { int v = cnt[i][tid]; cnt[i][tid] = run; run += v; }
        tot[tid] = run;
    }
    __syncthreads();
    if (tid == 0) {
        int acc = 0;
        for (int e = 0; e < 8; e++) { base[e] = acc; acc += tot[e]; }
        base[8] = acc;
        for (int e = 0; e <= 8; e++) g_expert_off[e] = base[e];
    }
    __syncthreads();

    int run2[8];
    #pragma unroll
    for (int e = 0; e < 8; e++) run2[e] = base[e] + cnt[tid][e];
    for (int i = 0; i < 32; i++) {
        int a = a0 + i;
        int e = g_tok_exp[a];
        int p = run2[e]++;
        g_perm_tok[p] = a >> 1;
        g_inv_pos[a]  = p;
    }
}

// ---------------------------------------------------------------------------
// fp16 mma.sync GEMM, BM=128 x BN_ tile, BK=32 halves, 5-stage cp.async,
// ldmatrix fragments. Warp grid 2x4; warp tile 64 x (BN_/4).
// IS_FC: A = gathered g_xh (K=1024), Out = half(gelu(D+b)) -> g_hbufh
// else:  A = g_hbufh (K=4096),       Out = D + b (fp32)    -> g_ybuf
// ---------------------------------------------------------------------------
template<int K, int NTOT, int BN_, bool IS_FC>
__global__ void __launch_bounds__(256) moe_gemm_fp16(
    const __half* __restrict__ A,
    const __half* __restrict__ W,
    const float* __restrict__ bias)
{
    constexpr int NCH    = K / BK;
    constexpr int NFRAG  = BN_ / 32;           // n-frags per warp (8 or 4)
    constexpr int B_ROWB = BN_ * 2;            // bytes per B smem row
    constexpr int B_BYTES = 32 * B_ROWB;       // 16384 or 8192
    constexpr int STAGE_BYTES = A_BYTES + B_BYTES;
    constexpr int NB = BN_ / 64;               // B chunks per thread (4 or 2)

    extern __shared__ char smem[];
    int e = blockIdx.y >> 6, m = blockIdx.y & 63;
    int off = g_expert_off[e];
    int cnt = g_expert_off[e+1] - off;
    if (m * BM >= cnt) return;
    int mbase = off + m * BM;
    int rv = min(cnt - m * BM, BM);
    int n0 = blockIdx.x * BN_;

    int tid = threadIdx.x;
    int lane = tid & 31, wid = tid >> 5;
    int wm = wid & 1, wn = wid >> 1;
    int g = lane >> 2, tig = lane & 3;

    uint32_t sbase = smem_u32(smem);
    const __half* wbase = W + (size_t)e * K * NTOT + n0;

    // ---- staging descriptors ----
    // A: 128 rows x 4 chunks(16B); 512 chunks, 2/thread
    const char* aSrc[2]; uint32_t aDst[2];
    #pragma unroll
    for (int i = 0; i < 2; i++) {
        int idx = i*256 + tid;
        int r = idx >> 2, c = idx & 3;
        int rr = min(r, rv - 1);
        int arow = IS_FC ? g_perm_tok[mbase + rr] : (mbase + rr);
        aSrc[i] = (const char*)(A + (size_t)arow * K) + c*16;
        aDst[i] = (uint32_t)(r*64 + ((c ^ ((r>>1)&3))*16));
    }
    // B: 32 rows x (BN_/8) chunks; NB/thread
    const char* bSrc[NB]; uint32_t bDst[NB];
    #pragma unroll
    for (int i = 0; i < NB; i++) {
        int idx = i*256 + tid;
        int k = idx / (BN_/8), nc = idx % (BN_/8);
        bSrc[i] = (const char*)(wbase + (size_t)k * NTOT) + nc*16;
        bDst[i] = (uint32_t)(k*B_ROWB + ((nc ^ (k&7))*16));
    }

    float acc[4][NFRAG][4];
    #pragma unroll
    for (int i = 0; i < 4; i++)
        #pragma unroll
        for (int j = 0; j < NFRAG; j++)
            #pragma unroll
            for (int v = 0; v < 4; v++) acc[i][j][v] = 0.0f;

    auto issue = [&](int kt) {
        uint32_t base = sbase + (uint32_t)(kt % NSTAGE) * STAGE_BYTES;
        #pragma unroll
        for (int i = 0; i < 2; i++)
            CP_ASYNC16(base + aDst[i], aSrc[i] + (size_t)kt * 64);
        #pragma unroll
        for (int i = 0; i < NB; i++)
            CP_ASYNC16(base + A_BYTES + bDst[i],
                       bSrc[i] + (size_t)kt * ((size_t)BK * NTOT * 2));
    };

    issue(0); CP_COMMIT();
    issue(1); CP_COMMIT();
    issue(2); CP_COMMIT();
    issue(3); CP_COMMIT();

    // ---- ldmatrix address components (per-lane constants) ----
    int rA  = wm*64 + (lane & 15);          // A row (before mf*16)
    int sA  = (rA >> 1) & 3;                // A swizzle selector
    int lc  = lane >> 4;                    // 0/1: which 8-chunk half
    int kB15 = lane & 15;                   // B row within k16
    int k7  = lane & 7;                     // B swizzle selector

    for (int kt = 0; kt < NCH; kt++) {
        CP_WAIT3();
        __syncthreads();
        if (kt + 4 < NCH) issue(kt + 4);
        CP_COMMIT();

        uint32_t aBase = sbase + (uint32_t)(kt % NSTAGE) * STAGE_BYTES;
        uint32_t bBase = aBase + A_BYTES;

        #pragma unroll
        for (int ks = 0; ks < 2; ks++) {
            uint32_t af[4][4];
            #pragma unroll
            for (int mf = 0; mf < 4; mf++) {
                uint32_t addr = aBase + (uint32_t)((rA + mf*16)*64
                              + (((ks*2 + lc) ^ sA) * 16));
                LDSM_X4(af[mf][0], af[mf][1], af[mf][2], af[mf][3], addr);
            }
            uint32_t bf[NFRAG][2];
            #pragma unroll
            for (int nf2 = 0; nf2 < NFRAG/2; nf2++) {
                int k  = ks*16 + kB15;
                int nc = wn*NFRAG + nf2*2 + lc;
                uint32_t addr = bBase + (uint32_t)(k*B_ROWB + ((nc ^ k7)*16));
                LDSM_X4_T(bf[2*nf2][0], bf[2*nf2][1], bf[2*nf2+1][0], bf[2*nf2+1][1], addr);
            }
            #pragma unroll
            for (int mf = 0; mf < 4; mf++)
                #pragma unroll
                for (int nf = 0; nf < NFRAG; nf++)
                    mma_fp16(acc[mf][nf], af[mf], bf[nf]);
        }
    }

    // ---- epilogue ----
    const float* brow = bias + (size_t)e * NTOT + n0;

    #pragma unroll
    for (int mf = 0; mf < 4; mf++) {
        int r0 = wm*64 + mf*16 + g;
        int r1 = r0 + 8;
        #pragma unroll
        for (int nf = 0; nf < NFRAG; nf++) {
            int col = wn*(NFRAG*8) + nf*8 + tig*2;
            float2 bb = *reinterpret_cast<const float2*>(brow + col);
            if (IS_FC) {
                __half2* o0 = reinterpret_cast<__half2*>(g_hbufh + (size_t)(mbase + r0) * NTOT + n0 + col);
                __half2* o1 = reinterpret_cast<__half2*>(g_hbufh + (size_t)(mbase + r1) * NTOT + n0 + col);
                if (r0 < rv)
                    *o0 = __floats2half2_rn(gelu_tanh(acc[mf][nf][0] + bb.x),
                                            gelu_tanh(acc[mf][nf][1] + bb.y));
                if (r1 < rv)
                    *o1 = __floats2half2_rn(gelu_tanh(acc[mf][nf][2] + bb.x),
                                            gelu_tanh(acc[mf][nf][3] + bb.y));
            } else {
                float* o0 = g_ybuf + (size_t)(mbase + r0) * NTOT + n0 + col;
                float* o1 = g_ybuf + (size_t)(mbase + r1) * NTOT + n0 + col;
                if (r0 < rv) {
                    float2 o; o.x = acc[mf][nf][0] + bb.x; o.y = acc[mf][nf][1] + bb.y;
                    *reinterpret_cast<float2*>(o0) = o;
                }
                if (r1 < rv) {
                    float2 o; o.x = acc[mf][nf][2] + bb.x; o.y = acc[mf][nf][3] + bb.y;
                    *reinterpret_cast<float2*>(o1) = o;
                }
            }
        }
    }
}

// ---------------------------------------------------------------------------
// Combine: out[t] = g0 * y[p0] + g1 * y[p1]
// ---------------------------------------------------------------------------
__global__ void __launch_bounds__(256) combine_kernel(float* __restrict__ out)
{
    int t = blockIdx.x;
    int j = threadIdx.x;
    int p0 = g_inv_pos[2*t], p1 = g_inv_pos[2*t+1];
    float g0 = g_tok_gate[2*t], g1 = g_tok_gate[2*t+1];
    const float4* y0 = reinterpret_cast<const float4*>(g_ybuf + (size_t)p0 * DMODEL);
    const float4* y1 = reinterpret_cast<const float4*>(g_ybuf + (size_t)p1 * DMODEL);
    float4 a = y0[j], b = y1[j];
    float4 o;
    o.x = g0*a.x + g1*b.x; o.y = g0*a.y + g1*b.y;
    o.z = g0*a.z + g1*b.z; o.w = g0*a.w + g1*b.w;
    reinterpret_cast<float4*>(out + (size_t)t * DMODEL)[j] = o;
}

// ---------------------------------------------------------------------------
extern "C" void kernel_launch(void* const* d_in, const int* in_sizes, int n_in,
                              void* d_out, int out_size)
{
    const float* x      = (const float*)d_in[0];
    const float* noise  = (const float*)d_in[1];
    const float* wroute = (const float*)d_in[2];
    const float* broute = (const float*)d_in[3];
    const float* wnoise = (const float*)d_in[4];
    const float* bnoise = (const float*)d_in[5];
    const float* wfc    = (const float*)d_in[6];
    const float* bfc    = (const float*)d_in[7];
    const float* wproj  = (const float*)d_in[8];
    const float* bproj  = (const float*)d_in[9];

    float* out   = (float*)d_out;
    float* gate1 = out + (size_t)TOK * DMODEL;

    constexpr int SMEM_G1 = NSTAGE * (A_BYTES + 32*256*2);   // 122880
    constexpr int SMEM_G2 = NSTAGE * (A_BYTES + 32*128*2);   // 81920

    cudaFuncSetAttribute((const void*)moe_gemm_fp16<DMODEL, HDIM, 256, true>,
        cudaFuncAttributeMaxDynamicSharedMemorySize, SMEM_G1);
    cudaFuncSetAttribute((const void*)moe_gemm_fp16<HDIM, DMODEL, 128, false>,
        cudaFuncAttributeMaxDynamicSharedMemorySize, SMEM_G2);

    __half *xh_p, *wfch_p, *wprojh_p, *hbufh_p;
    cudaGetSymbolAddress((void**)&xh_p, g_xh);
    cudaGetSymbolAddress((void**)&wfch_p, g_wfch);
    cudaGetSymbolAddress((void**)&wprojh_p, g_wprojh);
    cudaGetSymbolAddress((void**)&hbufh_p, g_hbufh);

    // fp32 -> fp16 conversion
    conv_half_kernel<<<592, 256>>>(x, xh_p, TOK*DMODEL/4);
    conv_half_kernel<<<4736, 256>>>(wfc, wfch_p, NEXP*DMODEL*HDIM/4);
    conv_half_kernel<<<4736, 256>>>(wproj, wprojh_p, NEXP*HDIM*DMODEL/4);

    router_kernel<<<TOK/8, 256>>>(x, noise, wroute, broute, wnoise, bnoise, gate1);
    partition_kernel<<<1, 256>>>();

    dim3 g1(HDIM / 256, NEXP * 64);    // 16 x 512
    moe_gemm_fp16<DMODEL, HDIM, 256, true><<<g1, 256, SMEM_G1>>>(xh_p, wfch_p, bfc);

    dim3 g2(DMODEL / 128, NEXP * 64);  // 8 x 512
    moe_gemm_fp16<HDIM, DMODEL, 128, false><<<g2, 256, SMEM_G2>>>(hbufh_p, wprojh_p, bproj);

    combine_kernel<<<TOK, 256>>>(out);
}